// round 13
// baseline (speedup 1.0000x reference)
#include <cuda_runtime.h>
#include <cuda_fp16.h>
#include <cstdint>

#define D 128
#define DV 32          // D / 4 (float4)
#define EPS 1e-5f
#define NT 64          // nodes per MLP block
#define PA 136         // fp16 tile pitch (272B rows -> conflict-free LDSM)
#define PS 132         // f32 h2 tile pitch
#define MAXN 50000

// Device scratch (allocation-free rule: __device__ globals)
__device__ float4 g_agg4[(size_t)MAXN * DV];   // aggregated messages [N][D]
__device__ float4 g_hln4[(size_t)MAXN * DV];   // post-LayerNorm h    [N][D]
__device__ uint2  g_nh16[(size_t)MAXN * DV];   // fp16 copy of node_hidden (4 h/entry)
__device__ float  g_colsum[D];
__device__ float  g_colsumsq[D];
// Pre-packed fp16 weights in B-fragment register order:
// [kt(8)][nsub(16)][lane(32)] -> uint2{b0,b1}
__device__ uint2  g_w1p[4096];
__device__ uint2  g_w2p[4096];

// SMEM for k_mlp: fp16 tile 64 x PA (17408 B); sS (64 x PS f32 = 33792 B)
// overlays it post-GEMM, so total is sized for sS.
#define SMEM_TOTAL 34816

// ---------------------------------------------------------------------------
// helpers
// ---------------------------------------------------------------------------
__device__ __forceinline__ uint32_t smem_u32(const void* p) {
    return (uint32_t)__cvta_generic_to_shared(p);
}

__device__ __forceinline__ void ldsm_x4(uint32_t* r, uint32_t addr) {
    asm volatile("ldmatrix.sync.aligned.m8n8.x4.shared.b16 {%0,%1,%2,%3}, [%4];"
                 : "=r"(r[0]), "=r"(r[1]), "=r"(r[2]), "=r"(r[3]) : "r"(addr));
}

__device__ __forceinline__ void mma_h(float* d, const uint32_t* a,
                                      const uint32_t* b) {
    asm volatile(
        "mma.sync.aligned.m16n8k16.row.col.f32.f16.f16.f32 "
        "{%0,%1,%2,%3}, {%4,%5,%6,%7}, {%8,%9}, {%0,%1,%2,%3};"
        : "+f"(d[0]), "+f"(d[1]), "+f"(d[2]), "+f"(d[3])
        : "r"(a[0]), "r"(a[1]), "r"(a[2]), "r"(a[3]), "r"(b[0]), "r"(b[1]));
}

__device__ __forceinline__ uint32_t h2(float a, float b) {
    __half2 h; h.x = __float2half_rn(a); h.y = __float2half_rn(b);
    return *(uint32_t*)&h;
}

// ---------------------------------------------------------------------------
// K0: zero agg (L2-warm for the scatter atomics) + stats, build fp16 nh table,
// pack weights. 4 float4 per thread; first 16 blocks pack W1/W2.
// ---------------------------------------------------------------------------
__global__ void k_pre(const float* __restrict__ nh,
                      const float* __restrict__ w1, const float* __restrict__ w2,
                      int total4) {
    int idx = blockIdx.x * blockDim.x + threadIdx.x;
    int base = blockIdx.x * 1024 + threadIdx.x;
    #pragma unroll
    for (int u = 0; u < 4; ++u) {
        int i = base + u * 256;
        if (i < total4) {
            g_agg4[i] = make_float4(0.f, 0.f, 0.f, 0.f);
            float4 v = ((const float4*)nh)[i];
            g_nh16[i] = make_uint2(h2(v.x, v.y), h2(v.z, v.w));
        }
    }
    if (idx < D) { g_colsum[idx] = 0.f; g_colsumsq[idx] = 0.f; }
    if (idx >= 4096) return;

    int lane = idx & 31;
    int nsub = (idx >> 5) & 15;
    int kt   = idx >> 9;
    int k0 = kt * 16 + (lane & 3) * 2;
    int n  = nsub * 8 + (lane >> 2);

    {
        uint2 q;
        q.x = h2(w1[(k0    ) * D + n], w1[(k0 + 1) * D + n]);
        q.y = h2(w1[(k0 + 8) * D + n], w1[(k0 + 9) * D + n]);
        g_w1p[idx] = q;
    }
    {
        uint2 q;
        q.x = h2(w2[(k0    ) * D + n], w2[(k0 + 1) * D + n]);
        q.y = h2(w2[(k0 + 8) * D + n], w2[(k0 + 9) * D + n]);
        g_w2p[idx] = q;
    }
}

// ---------------------------------------------------------------------------
// K1: scatter-add messages. nh gathered from the fp16 table (8B/lane, halves
// the gather LTS stream); eh fp32 streamed via __ldcs; accumulate fp32 REDG.
// edge_index is int32.
// ---------------------------------------------------------------------------
__global__ void k_scatter(const float* __restrict__ eh,
                          const int* __restrict__ ei,
                          int E) {
    int gw   = (blockIdx.x * blockDim.x + threadIdx.x) >> 5;
    int lane = threadIdx.x & 31;
    if (gw >= E) return;
    int src = ei[gw];
    int dst = ei[E + gw];
    uint2 raw = g_nh16[(size_t)src * DV + lane];
    const float4* eh4 = (const float4*)(eh + (size_t)gw * D);
    float4 b = __ldcs(eh4 + lane);
    float2 f0 = __half22float2(*(__half2*)&raw.x);
    float2 f1 = __half22float2(*(__half2*)&raw.y);
    float4 v = make_float4(f0.x + b.x, f0.y + b.y, f1.x + b.z, f1.y + b.w);
    float* p = (float*)(g_agg4 + (size_t)dst * DV) + lane * 4;
    asm volatile("red.global.add.v4.f32 [%0], {%1, %2, %3, %4};"
                 :: "l"(p), "f"(v.x), "f"(v.y), "f"(v.z), "f"(v.w)
                 : "memory");
}

// ---------------------------------------------------------------------------
// K2: tensor-core MLP, NT=64 nodes/block, 8 warps. Pure fp16 operands
// (f32 accumulate). Warp w: mh = w & 1 (32-row half), nq = w >> 1 (quarter).
// ---------------------------------------------------------------------------
__global__ void k_mlp(const float* __restrict__ b1, const float* __restrict__ b2,
                      const float* __restrict__ lng, const float* __restrict__ lnb,
                      int N) {
    extern __shared__ char sb[];
    __half* sHi = (__half*)(sb);
    float*  sS  = (float*)(sb);
    float*  sPartS = (float*)(sb);
    float*  sPartQ = (float*)(sb + 4096);

    const int t    = threadIdx.x;
    const int lane = t & 31;
    const int w    = t >> 5;
    const int nodeBase = blockIdx.x * NT;

    // ---- load agg tile (64 nodes) as fp16 ----
    {
        int n  = t >> 2;             // 0..63
        int k0 = (t & 3) * 32;       // 0,32,64,96
        int gn = nodeBase + n;
        __half* rowHi = sHi + n * PA;
        #pragma unroll
        for (int i = 0; i < 8; ++i) {
            float4 v = make_float4(0.f, 0.f, 0.f, 0.f);
            if (gn < N) v = g_agg4[(size_t)gn * DV + (k0 >> 2) + i];
            int kk = k0 + i * 4;
            *(uint32_t*)((char*)(rowHi + kk))     = h2(v.x, v.y);
            *(uint32_t*)((char*)(rowHi + kk + 2)) = h2(v.z, v.w);
        }
    }
    __syncthreads();

    const int mh = w & 1;            // 32-row half
    const int nq = w >> 1;           // 32-col quarter
    const uint32_t aB0 = smem_u32(sHi + (mh * 32 + (lane & 15)) * PA) + (lane >> 4) * 16;
    const uint32_t aB1 = aB0 + 16 * PA * 2;   // +16 rows

    float acc[32];
    #pragma unroll
    for (int i = 0; i < 32; ++i) acc[i] = 0.f;

    // ---- layer 1: h1 = relu(agg @ W1 + b1) ----
    #pragma unroll
    for (int kt = 0; kt < 8; ++kt) {
        uint32_t a0h[4], a1h[4];
        ldsm_x4(a0h, aB0 + kt * 32);
        ldsm_x4(a1h, aB1 + kt * 32);
        #pragma unroll
        for (int s = 0; s < 4; ++s) {
            uint2 q = g_w1p[(kt * 16 + nq * 4 + s) * 32 + lane];
            mma_h(acc + 4 * s,      a0h, &q.x);
            mma_h(acc + 16 + 4 * s, a1h, &q.x);
        }
    }
    __syncthreads();                 // everyone done reading A -> overwrite with H
    #pragma unroll
    for (int m = 0; m < 2; ++m) {
        #pragma unroll
        for (int s = 0; s < 4; ++s) {
            int cb = nq * 32 + s * 8 + (lane & 3) * 2;
            int r0 = mh * 32 + m * 16 + (lane >> 2);
            float2 bb = *(const float2*)(b1 + cb);
            float v00 = fmaxf(acc[16*m + 4*s + 0] + bb.x, 0.f);
            float v01 = fmaxf(acc[16*m + 4*s + 1] + bb.y, 0.f);
            float v10 = fmaxf(acc[16*m + 4*s + 2] + bb.x, 0.f);
            float v11 = fmaxf(acc[16*m + 4*s + 3] + bb.y, 0.f);
            *(uint32_t*)((char*)(sHi + r0 * PA + cb))       = h2(v00, v01);
            *(uint32_t*)((char*)(sHi + (r0 + 8) * PA + cb)) = h2(v10, v11);
        }
    }
    __syncthreads();

    #pragma unroll
    for (int i = 0; i < 32; ++i) acc[i] = 0.f;

    // ---- layer 2: h2 = h1 @ W2 + b2 (H lives in the A region) ----
    #pragma unroll
    for (int kt = 0; kt < 8; ++kt) {
        uint32_t a0h[4], a1h[4];
        ldsm_x4(a0h, aB0 + kt * 32);
        ldsm_x4(a1h, aB1 + kt * 32);
        #pragma unroll
        for (int s = 0; s < 4; ++s) {
            uint2 q = g_w2p[(kt * 16 + nq * 4 + s) * 32 + lane];
            mma_h(acc + 4 * s,      a0h, &q.x);
            mma_h(acc + 16 + 4 * s, a1h, &q.x);
        }
    }
    __syncthreads();                 // H dead -> overwrite with sS
    #pragma unroll
    for (int m = 0; m < 2; ++m) {
        #pragma unroll
        for (int s = 0; s < 4; ++s) {
            int cb = nq * 32 + s * 8 + (lane & 3) * 2;
            int r0 = mh * 32 + m * 16 + (lane >> 2);
            float2 bb = *(const float2*)(b2 + cb);
            *(float2*)(sS + r0 * PS + cb)       = make_float2(acc[16*m + 4*s + 0] + bb.x,
                                                              acc[16*m + 4*s + 1] + bb.y);
            *(float2*)(sS + (r0 + 8) * PS + cb) = make_float2(acc[16*m + 4*s + 2] + bb.x,
                                                              acc[16*m + 4*s + 3] + bb.y);
        }
    }
    __syncthreads();

    // ---- LayerNorm per node (warp per node, 8 nodes/warp) + column partials ----
    float colS[4] = {0.f, 0.f, 0.f, 0.f};
    float colQ[4] = {0.f, 0.f, 0.f, 0.f};

    #pragma unroll
    for (int r = 0; r < 8; ++r) {
        int n  = w + r * 8;          // 0..63
        int gn = nodeBase + n;
        float v0 = sS[n * PS + lane];
        float v1 = sS[n * PS + lane + 32];
        float v2 = sS[n * PS + lane + 64];
        float v3 = sS[n * PS + lane + 96];
        float s = v0 + v1 + v2 + v3;
        float q = v0*v0 + v1*v1 + v2*v2 + v3*v3;
        #pragma unroll
        for (int o = 16; o; o >>= 1) {
            s += __shfl_xor_sync(0xFFFFFFFFu, s, o);
            q += __shfl_xor_sync(0xFFFFFFFFu, q, o);
        }
        float mu  = s * (1.f / 128.f);
        float var = q * (1.f / 128.f) - mu * mu;
        float inv = rsqrtf(var + EPS);
        if (gn < N) {
            float y0 = (v0 - mu) * inv * lng[lane]      + lnb[lane];
            float y1 = (v1 - mu) * inv * lng[lane + 32] + lnb[lane + 32];
            float y2 = (v2 - mu) * inv * lng[lane + 64] + lnb[lane + 64];
            float y3 = (v3 - mu) * inv * lng[lane + 96] + lnb[lane + 96];
            float* hp = (float*)(g_hln4 + (size_t)gn * DV);
            hp[lane]      = y0;
            hp[lane + 32] = y1;
            hp[lane + 64] = y2;
            hp[lane + 96] = y3;
            colS[0] += y0; colQ[0] += y0 * y0;
            colS[1] += y1; colQ[1] += y1 * y1;
            colS[2] += y2; colQ[2] += y2 * y2;
            colS[3] += y3; colQ[3] += y3 * y3;
        }
    }
    __syncthreads();                 // sS dead -> partials
    #pragma unroll
    for (int qq = 0; qq < 4; ++qq) {
        sPartS[w * D + lane + 32 * qq] = colS[qq];
        sPartQ[w * D + lane + 32 * qq] = colQ[qq];
    }
    __syncthreads();
    if (t < D) {
        float s = 0.f, q = 0.f;
        #pragma unroll
        for (int w8 = 0; w8 < 8; ++w8) {
            s += sPartS[w8 * D + t];
            q += sPartQ[w8 * D + t];
        }
        atomicAdd(&g_colsum[t], s);
        atomicAdd(&g_colsumsq[t], q);
    }
}

// ---------------------------------------------------------------------------
// K4: out = relu((hln - ms*gmu) * mul + gn_b) + node_hidden.
// All three big streams are touch-once -> streaming hints.
// ---------------------------------------------------------------------------
__global__ void k_final(const float* __restrict__ nh,
                        const float* __restrict__ gnw,
                        const float* __restrict__ gnb,
                        const float* __restrict__ gnms,
                        float invN,
                        float* __restrict__ out,
                        int total4) {
    __shared__ float sMul[D], sSub[D], sB[D];
    int t = threadIdx.x;
    if (t < D) {
        float gmu = g_colsum[t] * invN;
        float e2  = g_colsumsq[t] * invN;
        float ms  = gnms[t];
        float gvar = e2 - 2.f * ms * gmu * gmu + ms * ms * gmu * gmu;
        sMul[t] = rsqrtf(gvar + EPS) * gnw[t];
        sSub[t] = ms * gmu;
        sB[t]   = gnb[t];
    }
    __syncthreads();
    int base = blockIdx.x * 512 + t;
    #pragma unroll
    for (int u = 0; u < 2; ++u) {
        int i = base + u * 256;
        if (i >= total4) break;
        int c4 = (i & (DV - 1)) * 4;
        float4 h = __ldcs(&g_hln4[i]);
        float4 x = __ldcs(((const float4*)nh) + i);
        float4 o;
        o.x = fmaxf((h.x - sSub[c4 + 0]) * sMul[c4 + 0] + sB[c4 + 0], 0.f) + x.x;
        o.y = fmaxf((h.y - sSub[c4 + 1]) * sMul[c4 + 1] + sB[c4 + 1], 0.f) + x.y;
        o.z = fmaxf((h.z - sSub[c4 + 2]) * sMul[c4 + 2] + sB[c4 + 2], 0.f) + x.z;
        o.w = fmaxf((h.w - sSub[c4 + 3]) * sMul[c4 + 3] + sB[c4 + 3], 0.f) + x.w;
        __stcs(((float4*)out) + i, o);
    }
}

// ---------------------------------------------------------------------------
extern "C" void kernel_launch(void* const* d_in, const int* in_sizes, int n_in,
                              void* d_out, int out_size) {
    const float* nh   = (const float*)d_in[0];
    const float* eh   = (const float*)d_in[1];
    const float* w1   = (const float*)d_in[2];
    const float* b1   = (const float*)d_in[3];
    const float* w2   = (const float*)d_in[4];
    const float* b2   = (const float*)d_in[5];
    const float* lng  = (const float*)d_in[6];
    const float* lnb  = (const float*)d_in[7];
    const float* gnw  = (const float*)d_in[8];
    const float* gnb  = (const float*)d_in[9];
    const float* gnms = (const float*)d_in[10];
    const int*   ei   = (const int*)d_in[11];

    int N = in_sizes[0] / D;
    int E = in_sizes[1] / D;
    int total4 = N * DV;

    cudaFuncSetAttribute(k_mlp, cudaFuncAttributeMaxDynamicSharedMemorySize, SMEM_TOTAL);

    k_pre<<<(total4 + 1023) / 1024, 256>>>(nh, w1, w2, total4);
    k_scatter<<<(E + 7) / 8, 256>>>(eh, ei, E);
    k_mlp<<<(N + NT - 1) / NT, 256, SMEM_TOTAL>>>(b1, b2, lng, lnb, N);
    k_final<<<(total4 + 511) / 512, 256>>>(nh, gnw, gnb, gnms, 1.f / (float)N,
                                           (float*)d_out, total4);
}

// round 14
// speedup vs baseline: 1.3801x; 1.3801x over previous
#include <cuda_runtime.h>
#include <cuda_fp16.h>
#include <cstdint>

#define D 128
#define DV 32          // D / 4 (float4)
#define EPS 1e-5f
#define NT 64          // nodes per MLP block
#define PA 136         // fp16 tile pitch (272B rows -> conflict-free LDSM)
#define PS 132         // f32 h2 tile pitch
#define MAXN 50000

// Device scratch (allocation-free rule: __device__ globals)
__device__ uint4  g_agg16[(size_t)MAXN * 16];  // fp16 agg [N][128h], 256B/node
__device__ uint4  g_nh16[(size_t)MAXN * 16];   // fp16 node_hidden, 256B/node
__device__ float4 g_hln4[(size_t)MAXN * DV];   // post-LayerNorm h [N][D]
__device__ float  g_colsum[D];
__device__ float  g_colsumsq[D];
// Pre-packed fp16 weights in B-fragment register order:
// [kt(8)][nsub(16)][lane(32)] -> uint2{b0,b1}
__device__ uint2  g_w1p[4096];
__device__ uint2  g_w2p[4096];

// SMEM for k_mlp: fp16 tile 64 x PA (17408 B); sS (64 x PS f32 = 33792 B)
// overlays it post-GEMM, so total is sized for sS.
#define SMEM_TOTAL 34816

// ---------------------------------------------------------------------------
// helpers
// ---------------------------------------------------------------------------
__device__ __forceinline__ uint32_t smem_u32(const void* p) {
    return (uint32_t)__cvta_generic_to_shared(p);
}

__device__ __forceinline__ void ldsm_x4(uint32_t* r, uint32_t addr) {
    asm volatile("ldmatrix.sync.aligned.m8n8.x4.shared.b16 {%0,%1,%2,%3}, [%4];"
                 : "=r"(r[0]), "=r"(r[1]), "=r"(r[2]), "=r"(r[3]) : "r"(addr));
}

__device__ __forceinline__ void mma_h(float* d, const uint32_t* a,
                                      const uint32_t* b) {
    asm volatile(
        "mma.sync.aligned.m16n8k16.row.col.f32.f16.f16.f32 "
        "{%0,%1,%2,%3}, {%4,%5,%6,%7}, {%8,%9}, {%0,%1,%2,%3};"
        : "+f"(d[0]), "+f"(d[1]), "+f"(d[2]), "+f"(d[3])
        : "r"(a[0]), "r"(a[1]), "r"(a[2]), "r"(a[3]), "r"(b[0]), "r"(b[1]));
}

__device__ __forceinline__ uint32_t h2(float a, float b) {
    __half2 h; h.x = __float2half_rn(a); h.y = __float2half_rn(b);
    return *(uint32_t*)&h;
}

// ---------------------------------------------------------------------------
// K0: zero fp16 agg (L2-warm for scatter atomics) + stats, build fp16 nh
// table, pack weights. 4 uint4-chunks per thread; first 16 blocks pack W1/W2.
// chunk i covers node i>>4, channels (i&15)*8 .. +7  (nh float4 idx = 2*i).
// ---------------------------------------------------------------------------
__global__ void k_pre(const float* __restrict__ nh,
                      const float* __restrict__ w1, const float* __restrict__ w2,
                      int totalChunks) {
    int idx = blockIdx.x * blockDim.x + threadIdx.x;
    int base = blockIdx.x * 1024 + threadIdx.x;
    #pragma unroll
    for (int u = 0; u < 4; ++u) {
        int i = base + u * 256;
        if (i < totalChunks) {
            g_agg16[i] = make_uint4(0u, 0u, 0u, 0u);
            float4 a = ((const float4*)nh)[2 * i];
            float4 b = ((const float4*)nh)[2 * i + 1];
            g_nh16[i] = make_uint4(h2(a.x, a.y), h2(a.z, a.w),
                                   h2(b.x, b.y), h2(b.z, b.w));
        }
    }
    if (idx < D) { g_colsum[idx] = 0.f; g_colsumsq[idx] = 0.f; }
    if (idx >= 4096) return;

    int lane = idx & 31;
    int nsub = (idx >> 5) & 15;
    int kt   = idx >> 9;
    int k0 = kt * 16 + (lane & 3) * 2;
    int n  = nsub * 8 + (lane >> 2);

    {
        uint2 q;
        q.x = h2(w1[(k0    ) * D + n], w1[(k0 + 1) * D + n]);
        q.y = h2(w1[(k0 + 8) * D + n], w1[(k0 + 9) * D + n]);
        g_w1p[idx] = q;
    }
    {
        uint2 q;
        q.x = h2(w2[(k0    ) * D + n], w2[(k0 + 1) * D + n]);
        q.y = h2(w2[(k0 + 8) * D + n], w2[(k0 + 9) * D + n]);
        g_w2p[idx] = q;
    }
}

// ---------------------------------------------------------------------------
// K1: scatter-add messages, fp16 accumulation. 2 edges per warp (16 lanes
// each, 8 channels/lane). Math in fp32, rounded to fp16 before the atomic.
// red.global.add.noftz.v4.f16x2 = 16B/lane -> 16 REDG lanes per edge (half
// of the fp32 version). edge_index is int32.
// ---------------------------------------------------------------------------
__global__ void k_scatter(const float* __restrict__ eh,
                          const int* __restrict__ ei,
                          int E) {
    int gw   = (blockIdx.x * blockDim.x + threadIdx.x) >> 5;
    int lane = threadIdx.x & 31;
    int e    = gw * 2 + (lane >> 4);
    int lh   = lane & 15;
    if (e >= E) return;
    int src = ei[e];
    int dst = ei[E + e];
    uint4 nv = g_nh16[(size_t)src * 16 + lh];
    const float4* eh4 = (const float4*)(eh + (size_t)e * D) + lh * 2;
    float4 b0 = __ldcs(eh4);
    float4 b1 = __ldcs(eh4 + 1);
    float2 f0 = __half22float2(*(__half2*)&nv.x);
    float2 f1 = __half22float2(*(__half2*)&nv.y);
    float2 f2 = __half22float2(*(__half2*)&nv.z);
    float2 f3 = __half22float2(*(__half2*)&nv.w);
    uint32_t r0 = h2(f0.x + b0.x, f0.y + b0.y);
    uint32_t r1 = h2(f1.x + b0.z, f1.y + b0.w);
    uint32_t r2 = h2(f2.x + b1.x, f2.y + b1.y);
    uint32_t r3 = h2(f3.x + b1.z, f3.y + b1.w);
    uint4* p = &g_agg16[(size_t)dst * 16 + lh];
    asm volatile("red.global.add.noftz.v4.f16x2 [%0], {%1, %2, %3, %4};"
                 :: "l"(p), "r"(r0), "r"(r1), "r"(r2), "r"(r3)
                 : "memory");
}

// ---------------------------------------------------------------------------
// K2: tensor-core MLP, NT=64 nodes/block, 8 warps. Pure fp16 operands
// (f32 accumulate). agg tile read directly as fp16 (no conversion).
// Warp w: mh = w & 1 (32-row half), nq = w >> 1 (32-col quarter).
// ---------------------------------------------------------------------------
__global__ void k_mlp(const float* __restrict__ b1, const float* __restrict__ b2,
                      const float* __restrict__ lng, const float* __restrict__ lnb,
                      int N) {
    extern __shared__ char sb[];
    __half* sHi = (__half*)(sb);
    float*  sS  = (float*)(sb);
    float*  sPartS = (float*)(sb);
    float*  sPartQ = (float*)(sb + 4096);

    const int t    = threadIdx.x;
    const int lane = t & 31;
    const int w    = t >> 5;
    const int nodeBase = blockIdx.x * NT;

    // ---- load agg tile (64 nodes), fp16 passthrough ----
    {
        int n  = t >> 2;             // 0..63
        int k0 = (t & 3) * 32;       // 0,32,64,96
        int gn = nodeBase + n;
        __half* rowHi = sHi + n * PA;
        #pragma unroll
        for (int i = 0; i < 4; ++i) {
            uint4 v = make_uint4(0u, 0u, 0u, 0u);
            if (gn < N) v = g_agg16[(size_t)gn * 16 + (k0 >> 3) + i];
            *(uint4*)((char*)(rowHi + k0 + i * 8)) = v;
        }
    }
    __syncthreads();

    const int mh = w & 1;            // 32-row half
    const int nq = w >> 1;           // 32-col quarter
    const uint32_t aB0 = smem_u32(sHi + (mh * 32 + (lane & 15)) * PA) + (lane >> 4) * 16;
    const uint32_t aB1 = aB0 + 16 * PA * 2;   // +16 rows

    float acc[32];
    #pragma unroll
    for (int i = 0; i < 32; ++i) acc[i] = 0.f;

    // ---- layer 1: h1 = relu(agg @ W1 + b1) ----
    #pragma unroll
    for (int kt = 0; kt < 8; ++kt) {
        uint32_t a0h[4], a1h[4];
        ldsm_x4(a0h, aB0 + kt * 32);
        ldsm_x4(a1h, aB1 + kt * 32);
        #pragma unroll
        for (int s = 0; s < 4; ++s) {
            uint2 q = g_w1p[(kt * 16 + nq * 4 + s) * 32 + lane];
            mma_h(acc + 4 * s,      a0h, &q.x);
            mma_h(acc + 16 + 4 * s, a1h, &q.x);
        }
    }
    __syncthreads();                 // everyone done reading A -> overwrite with H
    #pragma unroll
    for (int m = 0; m < 2; ++m) {
        #pragma unroll
        for (int s = 0; s < 4; ++s) {
            int cb = nq * 32 + s * 8 + (lane & 3) * 2;
            int r0 = mh * 32 + m * 16 + (lane >> 2);
            float2 bb = *(const float2*)(b1 + cb);
            float v00 = fmaxf(acc[16*m + 4*s + 0] + bb.x, 0.f);
            float v01 = fmaxf(acc[16*m + 4*s + 1] + bb.y, 0.f);
            float v10 = fmaxf(acc[16*m + 4*s + 2] + bb.x, 0.f);
            float v11 = fmaxf(acc[16*m + 4*s + 3] + bb.y, 0.f);
            *(uint32_t*)((char*)(sHi + r0 * PA + cb))       = h2(v00, v01);
            *(uint32_t*)((char*)(sHi + (r0 + 8) * PA + cb)) = h2(v10, v11);
        }
    }
    __syncthreads();

    #pragma unroll
    for (int i = 0; i < 32; ++i) acc[i] = 0.f;

    // ---- layer 2: h2 = h1 @ W2 + b2 (H lives in the A region) ----
    #pragma unroll
    for (int kt = 0; kt < 8; ++kt) {
        uint32_t a0h[4], a1h[4];
        ldsm_x4(a0h, aB0 + kt * 32);
        ldsm_x4(a1h, aB1 + kt * 32);
        #pragma unroll
        for (int s = 0; s < 4; ++s) {
            uint2 q = g_w2p[(kt * 16 + nq * 4 + s) * 32 + lane];
            mma_h(acc + 4 * s,      a0h, &q.x);
            mma_h(acc + 16 + 4 * s, a1h, &q.x);
        }
    }
    __syncthreads();                 // H dead -> overwrite with sS
    #pragma unroll
    for (int m = 0; m < 2; ++m) {
        #pragma unroll
        for (int s = 0; s < 4; ++s) {
            int cb = nq * 32 + s * 8 + (lane & 3) * 2;
            int r0 = mh * 32 + m * 16 + (lane >> 2);
            float2 bb = *(const float2*)(b2 + cb);
            *(float2*)(sS + r0 * PS + cb)       = make_float2(acc[16*m + 4*s + 0] + bb.x,
                                                              acc[16*m + 4*s + 1] + bb.y);
            *(float2*)(sS + (r0 + 8) * PS + cb) = make_float2(acc[16*m + 4*s + 2] + bb.x,
                                                              acc[16*m + 4*s + 3] + bb.y);
        }
    }
    __syncthreads();

    // ---- LayerNorm per node (warp per node, 8 nodes/warp) + column partials ----
    float colS[4] = {0.f, 0.f, 0.f, 0.f};
    float colQ[4] = {0.f, 0.f, 0.f, 0.f};

    #pragma unroll
    for (int r = 0; r < 8; ++r) {
        int n  = w + r * 8;          // 0..63
        int gn = nodeBase + n;
        float v0 = sS[n * PS + lane];
        float v1 = sS[n * PS + lane + 32];
        float v2 = sS[n * PS + lane + 64];
        float v3 = sS[n * PS + lane + 96];
        float s = v0 + v1 + v2 + v3;
        float q = v0*v0 + v1*v1 + v2*v2 + v3*v3;
        #pragma unroll
        for (int o = 16; o; o >>= 1) {
            s += __shfl_xor_sync(0xFFFFFFFFu, s, o);
            q += __shfl_xor_sync(0xFFFFFFFFu, q, o);
        }
        float mu  = s * (1.f / 128.f);
        float var = q * (1.f / 128.f) - mu * mu;
        float inv = rsqrtf(var + EPS);
        if (gn < N) {
            float y0 = (v0 - mu) * inv * lng[lane]      + lnb[lane];
            float y1 = (v1 - mu) * inv * lng[lane + 32] + lnb[lane + 32];
            float y2 = (v2 - mu) * inv * lng[lane + 64] + lnb[lane + 64];
            float y3 = (v3 - mu) * inv * lng[lane + 96] + lnb[lane + 96];
            float* hp = (float*)(g_hln4 + (size_t)gn * DV);
            hp[lane]      = y0;
            hp[lane + 32] = y1;
            hp[lane + 64] = y2;
            hp[lane + 96] = y3;
            colS[0] += y0; colQ[0] += y0 * y0;
            colS[1] += y1; colQ[1] += y1 * y1;
            colS[2] += y2; colQ[2] += y2 * y2;
            colS[3] += y3; colQ[3] += y3 * y3;
        }
    }
    __syncthreads();                 // sS dead -> partials
    #pragma unroll
    for (int qq = 0; qq < 4; ++qq) {
        sPartS[w * D + lane + 32 * qq] = colS[qq];
        sPartQ[w * D + lane + 32 * qq] = colQ[qq];
    }
    __syncthreads();
    if (t < D) {
        float s = 0.f, q = 0.f;
        #pragma unroll
        for (int w8 = 0; w8 < 8; ++w8) {
            s += sPartS[w8 * D + t];
            q += sPartQ[w8 * D + t];
        }
        atomicAdd(&g_colsum[t], s);
        atomicAdd(&g_colsumsq[t], q);
    }
}

// ---------------------------------------------------------------------------
// K4: out = relu((hln - ms*gmu) * mul + gn_b) + node_hidden.
// 2 float4 per thread; plain loads (ldcs measured slower here).
// ---------------------------------------------------------------------------
__global__ void k_final(const float* __restrict__ nh,
                        const float* __restrict__ gnw,
                        const float* __restrict__ gnb,
                        const float* __restrict__ gnms,
                        float invN,
                        float* __restrict__ out,
                        int total4) {
    __shared__ float sMul[D], sSub[D], sB[D];
    int t = threadIdx.x;
    if (t < D) {
        float gmu = g_colsum[t] * invN;
        float e2  = g_colsumsq[t] * invN;
        float ms  = gnms[t];
        float gvar = e2 - 2.f * ms * gmu * gmu + ms * ms * gmu * gmu;
        sMul[t] = rsqrtf(gvar + EPS) * gnw[t];
        sSub[t] = ms * gmu;
        sB[t]   = gnb[t];
    }
    __syncthreads();
    int base = blockIdx.x * 512 + t;
    #pragma unroll
    for (int u = 0; u < 2; ++u) {
        int i = base + u * 256;
        if (i >= total4) break;
        int c4 = (i & (DV - 1)) * 4;
        float4 h = g_hln4[i];
        float4 x = ((const float4*)nh)[i];
        float4 o;
        o.x = fmaxf((h.x - sSub[c4 + 0]) * sMul[c4 + 0] + sB[c4 + 0], 0.f) + x.x;
        o.y = fmaxf((h.y - sSub[c4 + 1]) * sMul[c4 + 1] + sB[c4 + 1], 0.f) + x.y;
        o.z = fmaxf((h.z - sSub[c4 + 2]) * sMul[c4 + 2] + sB[c4 + 2], 0.f) + x.z;
        o.w = fmaxf((h.w - sSub[c4 + 3]) * sMul[c4 + 3] + sB[c4 + 3], 0.f) + x.w;
        ((float4*)out)[i] = o;
    }
}

// ---------------------------------------------------------------------------
extern "C" void kernel_launch(void* const* d_in, const int* in_sizes, int n_in,
                              void* d_out, int out_size) {
    const float* nh   = (const float*)d_in[0];
    const float* eh   = (const float*)d_in[1];
    const float* w1   = (const float*)d_in[2];
    const float* b1   = (const float*)d_in[3];
    const float* w2   = (const float*)d_in[4];
    const float* b2   = (const float*)d_in[5];
    const float* lng  = (const float*)d_in[6];
    const float* lnb  = (const float*)d_in[7];
    const float* gnw  = (const float*)d_in[8];
    const float* gnb  = (const float*)d_in[9];
    const float* gnms = (const float*)d_in[10];
    const int*   ei   = (const int*)d_in[11];

    int N = in_sizes[0] / D;
    int E = in_sizes[1] / D;
    int total4 = N * DV;
    int totalChunks = N * 16;

    cudaFuncSetAttribute(k_mlp, cudaFuncAttributeMaxDynamicSharedMemorySize, SMEM_TOTAL);

    k_pre<<<(totalChunks + 1023) / 1024, 256>>>(nh, w1, w2, totalChunks);
    k_scatter<<<(E + 15) / 16, 256>>>(eh, ei, E);
    k_mlp<<<(N + NT - 1) / NT, 256, SMEM_TOTAL>>>(b1, b2, lng, lnb, N);
    k_final<<<(total4 + 511) / 512, 256>>>(nh, gnw, gnb, gnms, 1.f / (float)N,
                                           (float*)d_out, total4);
}

// round 15
// speedup vs baseline: 1.4091x; 1.0211x over previous
#include <cuda_runtime.h>
#include <cuda_fp16.h>
#include <cstdint>

#define D 128
#define DV 32          // D / 4 (float4)
#define EPS 1e-5f
#define NT 64          // nodes per MLP block
#define PA 136         // fp16 tile pitch (272B rows -> conflict-free LDSM)
#define PS 132         // f32 h2 tile pitch
#define MAXN 50000

// Device scratch (allocation-free rule: __device__ globals)
__device__ uint4  g_agg16[(size_t)MAXN * 16];  // fp16 agg [N][128h], 256B/node
__device__ uint4  g_nh16[(size_t)MAXN * 16];   // fp16 node_hidden, 256B/node
__device__ __half g_hln16[(size_t)MAXN * D];   // fp16 post-LayerNorm h [N][D]
__device__ float  g_colsum[D];
__device__ float  g_colsumsq[D];
// Pre-packed fp16 weights in B-fragment register order:
// [kt(8)][nsub(16)][lane(32)] -> uint2{b0,b1}
__device__ uint2  g_w1p[4096];
__device__ uint2  g_w2p[4096];

// SMEM for k_mlp: fp16 tile 64 x PA (17408 B); sS (64 x PS f32 = 33792 B)
// overlays it post-GEMM, so total is sized for sS.
#define SMEM_TOTAL 34816

// ---------------------------------------------------------------------------
// helpers
// ---------------------------------------------------------------------------
__device__ __forceinline__ uint32_t smem_u32(const void* p) {
    return (uint32_t)__cvta_generic_to_shared(p);
}

__device__ __forceinline__ void ldsm_x4(uint32_t* r, uint32_t addr) {
    asm volatile("ldmatrix.sync.aligned.m8n8.x4.shared.b16 {%0,%1,%2,%3}, [%4];"
                 : "=r"(r[0]), "=r"(r[1]), "=r"(r[2]), "=r"(r[3]) : "r"(addr));
}

__device__ __forceinline__ void mma_h(float* d, const uint32_t* a,
                                      const uint32_t* b) {
    asm volatile(
        "mma.sync.aligned.m16n8k16.row.col.f32.f16.f16.f32 "
        "{%0,%1,%2,%3}, {%4,%5,%6,%7}, {%8,%9}, {%0,%1,%2,%3};"
        : "+f"(d[0]), "+f"(d[1]), "+f"(d[2]), "+f"(d[3])
        : "r"(a[0]), "r"(a[1]), "r"(a[2]), "r"(a[3]), "r"(b[0]), "r"(b[1]));
}

__device__ __forceinline__ uint32_t h2(float a, float b) {
    __half2 h; h.x = __float2half_rn(a); h.y = __float2half_rn(b);
    return *(uint32_t*)&h;
}

// ---------------------------------------------------------------------------
// K0: zero fp16 agg (L2-warm for scatter atomics) + stats, build fp16 nh
// table, pack weights. 4 uint4-chunks per thread; first 16 blocks pack W1/W2.
// ---------------------------------------------------------------------------
__global__ void k_pre(const float* __restrict__ nh,
                      const float* __restrict__ w1, const float* __restrict__ w2,
                      int totalChunks) {
    int idx = blockIdx.x * blockDim.x + threadIdx.x;
    int base = blockIdx.x * 1024 + threadIdx.x;
    #pragma unroll
    for (int u = 0; u < 4; ++u) {
        int i = base + u * 256;
        if (i < totalChunks) {
            g_agg16[i] = make_uint4(0u, 0u, 0u, 0u);
            float4 a = ((const float4*)nh)[2 * i];
            float4 b = ((const float4*)nh)[2 * i + 1];
            g_nh16[i] = make_uint4(h2(a.x, a.y), h2(a.z, a.w),
                                   h2(b.x, b.y), h2(b.z, b.w));
        }
    }
    if (idx < D) { g_colsum[idx] = 0.f; g_colsumsq[idx] = 0.f; }
    if (idx >= 4096) return;

    int lane = idx & 31;
    int nsub = (idx >> 5) & 15;
    int kt   = idx >> 9;
    int k0 = kt * 16 + (lane & 3) * 2;
    int n  = nsub * 8 + (lane >> 2);

    {
        uint2 q;
        q.x = h2(w1[(k0    ) * D + n], w1[(k0 + 1) * D + n]);
        q.y = h2(w1[(k0 + 8) * D + n], w1[(k0 + 9) * D + n]);
        g_w1p[idx] = q;
    }
    {
        uint2 q;
        q.x = h2(w2[(k0    ) * D + n], w2[(k0 + 1) * D + n]);
        q.y = h2(w2[(k0 + 8) * D + n], w2[(k0 + 9) * D + n]);
        g_w2p[idx] = q;
    }
}

// ---------------------------------------------------------------------------
// K1: scatter-add messages, fp16 accumulation. 2 edges per warp (16 lanes
// each, 8 channels/lane). Math in fp32, rounded to fp16 before the atomic.
// red.global.add.noftz.v4.f16x2 = 16B/lane -> 16 REDG lanes per edge.
// ---------------------------------------------------------------------------
__global__ void k_scatter(const float* __restrict__ eh,
                          const int* __restrict__ ei,
                          int E) {
    int gw   = (blockIdx.x * blockDim.x + threadIdx.x) >> 5;
    int lane = threadIdx.x & 31;
    int e    = gw * 2 + (lane >> 4);
    int lh   = lane & 15;
    if (e >= E) return;
    int src = ei[e];
    int dst = ei[E + e];
    uint4 nv = g_nh16[(size_t)src * 16 + lh];
    const float4* eh4 = (const float4*)(eh + (size_t)e * D) + lh * 2;
    float4 b0 = __ldcs(eh4);
    float4 b1 = __ldcs(eh4 + 1);
    float2 f0 = __half22float2(*(__half2*)&nv.x);
    float2 f1 = __half22float2(*(__half2*)&nv.y);
    float2 f2 = __half22float2(*(__half2*)&nv.z);
    float2 f3 = __half22float2(*(__half2*)&nv.w);
    uint32_t r0 = h2(f0.x + b0.x, f0.y + b0.y);
    uint32_t r1 = h2(f1.x + b0.z, f1.y + b0.w);
    uint32_t r2 = h2(f2.x + b1.x, f2.y + b1.y);
    uint32_t r3 = h2(f3.x + b1.z, f3.y + b1.w);
    uint4* p = &g_agg16[(size_t)dst * 16 + lh];
    asm volatile("red.global.add.noftz.v4.f16x2 [%0], {%1, %2, %3, %4};"
                 :: "l"(p), "r"(r0), "r"(r1), "r"(r2), "r"(r3)
                 : "memory");
}

// ---------------------------------------------------------------------------
// K2: tensor-core MLP, NT=64 nodes/block, 8 warps. Pure fp16 operands
// (f32 accumulate). agg tile read directly as fp16; hln written as fp16.
// Warp w: mh = w & 1 (32-row half), nq = w >> 1 (32-col quarter).
// ---------------------------------------------------------------------------
__global__ void k_mlp(const float* __restrict__ b1, const float* __restrict__ b2,
                      const float* __restrict__ lng, const float* __restrict__ lnb,
                      int N) {
    extern __shared__ char sb[];
    __half* sHi = (__half*)(sb);
    float*  sS  = (float*)(sb);
    float*  sPartS = (float*)(sb);
    float*  sPartQ = (float*)(sb + 4096);

    const int t    = threadIdx.x;
    const int lane = t & 31;
    const int w    = t >> 5;
    const int nodeBase = blockIdx.x * NT;

    // ---- load agg tile (64 nodes), fp16 passthrough ----
    {
        int n  = t >> 2;             // 0..63
        int k0 = (t & 3) * 32;       // 0,32,64,96
        int gn = nodeBase + n;
        __half* rowHi = sHi + n * PA;
        #pragma unroll
        for (int i = 0; i < 4; ++i) {
            uint4 v = make_uint4(0u, 0u, 0u, 0u);
            if (gn < N) v = g_agg16[(size_t)gn * 16 + (k0 >> 3) + i];
            *(uint4*)((char*)(rowHi + k0 + i * 8)) = v;
        }
    }
    __syncthreads();

    const int mh = w & 1;            // 32-row half
    const int nq = w >> 1;           // 32-col quarter
    const uint32_t aB0 = smem_u32(sHi + (mh * 32 + (lane & 15)) * PA) + (lane >> 4) * 16;
    const uint32_t aB1 = aB0 + 16 * PA * 2;   // +16 rows

    float acc[32];
    #pragma unroll
    for (int i = 0; i < 32; ++i) acc[i] = 0.f;

    // ---- layer 1: h1 = relu(agg @ W1 + b1) ----
    #pragma unroll
    for (int kt = 0; kt < 8; ++kt) {
        uint32_t a0h[4], a1h[4];
        ldsm_x4(a0h, aB0 + kt * 32);
        ldsm_x4(a1h, aB1 + kt * 32);
        #pragma unroll
        for (int s = 0; s < 4; ++s) {
            uint2 q = g_w1p[(kt * 16 + nq * 4 + s) * 32 + lane];
            mma_h(acc + 4 * s,      a0h, &q.x);
            mma_h(acc + 16 + 4 * s, a1h, &q.x);
        }
    }
    __syncthreads();                 // everyone done reading A -> overwrite with H
    #pragma unroll
    for (int m = 0; m < 2; ++m) {
        #pragma unroll
        for (int s = 0; s < 4; ++s) {
            int cb = nq * 32 + s * 8 + (lane & 3) * 2;
            int r0 = mh * 32 + m * 16 + (lane >> 2);
            float2 bb = *(const float2*)(b1 + cb);
            float v00 = fmaxf(acc[16*m + 4*s + 0] + bb.x, 0.f);
            float v01 = fmaxf(acc[16*m + 4*s + 1] + bb.y, 0.f);
            float v10 = fmaxf(acc[16*m + 4*s + 2] + bb.x, 0.f);
            float v11 = fmaxf(acc[16*m + 4*s + 3] + bb.y, 0.f);
            *(uint32_t*)((char*)(sHi + r0 * PA + cb))       = h2(v00, v01);
            *(uint32_t*)((char*)(sHi + (r0 + 8) * PA + cb)) = h2(v10, v11);
        }
    }
    __syncthreads();

    #pragma unroll
    for (int i = 0; i < 32; ++i) acc[i] = 0.f;

    // ---- layer 2: h2 = h1 @ W2 + b2 (H lives in the A region) ----
    #pragma unroll
    for (int kt = 0; kt < 8; ++kt) {
        uint32_t a0h[4], a1h[4];
        ldsm_x4(a0h, aB0 + kt * 32);
        ldsm_x4(a1h, aB1 + kt * 32);
        #pragma unroll
        for (int s = 0; s < 4; ++s) {
            uint2 q = g_w2p[(kt * 16 + nq * 4 + s) * 32 + lane];
            mma_h(acc + 4 * s,      a0h, &q.x);
            mma_h(acc + 16 + 4 * s, a1h, &q.x);
        }
    }
    __syncthreads();                 // H dead -> overwrite with sS
    #pragma unroll
    for (int m = 0; m < 2; ++m) {
        #pragma unroll
        for (int s = 0; s < 4; ++s) {
            int cb = nq * 32 + s * 8 + (lane & 3) * 2;
            int r0 = mh * 32 + m * 16 + (lane >> 2);
            float2 bb = *(const float2*)(b2 + cb);
            *(float2*)(sS + r0 * PS + cb)       = make_float2(acc[16*m + 4*s + 0] + bb.x,
                                                              acc[16*m + 4*s + 1] + bb.y);
            *(float2*)(sS + (r0 + 8) * PS + cb) = make_float2(acc[16*m + 4*s + 2] + bb.x,
                                                              acc[16*m + 4*s + 3] + bb.y);
        }
    }
    __syncthreads();

    // ---- LayerNorm per node (warp per node, 8 nodes/warp) + column partials ----
    float colS[4] = {0.f, 0.f, 0.f, 0.f};
    float colQ[4] = {0.f, 0.f, 0.f, 0.f};

    #pragma unroll
    for (int r = 0; r < 8; ++r) {
        int n  = w + r * 8;          // 0..63
        int gn = nodeBase + n;
        float v0 = sS[n * PS + lane];
        float v1 = sS[n * PS + lane + 32];
        float v2 = sS[n * PS + lane + 64];
        float v3 = sS[n * PS + lane + 96];
        float s = v0 + v1 + v2 + v3;
        float q = v0*v0 + v1*v1 + v2*v2 + v3*v3;
        #pragma unroll
        for (int o = 16; o; o >>= 1) {
            s += __shfl_xor_sync(0xFFFFFFFFu, s, o);
            q += __shfl_xor_sync(0xFFFFFFFFu, q, o);
        }
        float mu  = s * (1.f / 128.f);
        float var = q * (1.f / 128.f) - mu * mu;
        float inv = rsqrtf(var + EPS);
        if (gn < N) {
            float y0 = (v0 - mu) * inv * lng[lane]      + lnb[lane];
            float y1 = (v1 - mu) * inv * lng[lane + 32] + lnb[lane + 32];
            float y2 = (v2 - mu) * inv * lng[lane + 64] + lnb[lane + 64];
            float y3 = (v3 - mu) * inv * lng[lane + 96] + lnb[lane + 96];
            __half* hp = g_hln16 + (size_t)gn * D;
            hp[lane]      = __float2half_rn(y0);
            hp[lane + 32] = __float2half_rn(y1);
            hp[lane + 64] = __float2half_rn(y2);
            hp[lane + 96] = __float2half_rn(y3);
            colS[0] += y0; colQ[0] += y0 * y0;
            colS[1] += y1; colQ[1] += y1 * y1;
            colS[2] += y2; colQ[2] += y2 * y2;
            colS[3] += y3; colQ[3] += y3 * y3;
        }
    }
    __syncthreads();                 // sS dead -> partials
    #pragma unroll
    for (int qq = 0; qq < 4; ++qq) {
        sPartS[w * D + lane + 32 * qq] = colS[qq];
        sPartQ[w * D + lane + 32 * qq] = colQ[qq];
    }
    __syncthreads();
    if (t < D) {
        float s = 0.f, q = 0.f;
        #pragma unroll
        for (int w8 = 0; w8 < 8; ++w8) {
            s += sPartS[w8 * D + t];
            q += sPartQ[w8 * D + t];
        }
        atomicAdd(&g_colsum[t], s);
        atomicAdd(&g_colsumsq[t], q);
    }
}

// ---------------------------------------------------------------------------
// K4: out = relu((hln - ms*gmu) * mul + gn_b) + node_hidden.
// hln read as fp16 (uint2 = 4 channels, 8B); residual nh stays fp32.
// ---------------------------------------------------------------------------
__global__ void k_final(const float* __restrict__ nh,
                        const float* __restrict__ gnw,
                        const float* __restrict__ gnb,
                        const float* __restrict__ gnms,
                        float invN,
                        float* __restrict__ out,
                        int total4) {
    __shared__ float sMul[D], sSub[D], sB[D];
    int t = threadIdx.x;
    if (t < D) {
        float gmu = g_colsum[t] * invN;
        float e2  = g_colsumsq[t] * invN;
        float ms  = gnms[t];
        float gvar = e2 - 2.f * ms * gmu * gmu + ms * ms * gmu * gmu;
        sMul[t] = rsqrtf(gvar + EPS) * gnw[t];
        sSub[t] = ms * gmu;
        sB[t]   = gnb[t];
    }
    __syncthreads();
    int base = blockIdx.x * 512 + t;
    #pragma unroll
    for (int u = 0; u < 2; ++u) {
        int i = base + u * 256;
        if (i >= total4) break;
        int c4 = (i & (DV - 1)) * 4;
        uint2 hv = ((const uint2*)g_hln16)[i];
        float2 h0 = __half22float2(*(__half2*)&hv.x);
        float2 h1 = __half22float2(*(__half2*)&hv.y);
        float4 x = ((const float4*)nh)[i];
        float4 o;
        o.x = fmaxf((h0.x - sSub[c4 + 0]) * sMul[c4 + 0] + sB[c4 + 0], 0.f) + x.x;
        o.y = fmaxf((h0.y - sSub[c4 + 1]) * sMul[c4 + 1] + sB[c4 + 1], 0.f) + x.y;
        o.z = fmaxf((h1.x - sSub[c4 + 2]) * sMul[c4 + 2] + sB[c4 + 2], 0.f) + x.z;
        o.w = fmaxf((h1.y - sSub[c4 + 3]) * sMul[c4 + 3] + sB[c4 + 3], 0.f) + x.w;
        ((float4*)out)[i] = o;
    }
}

// ---------------------------------------------------------------------------
extern "C" void kernel_launch(void* const* d_in, const int* in_sizes, int n_in,
                              void* d_out, int out_size) {
    const float* nh   = (const float*)d_in[0];
    const float* eh   = (const float*)d_in[1];
    const float* w1   = (const float*)d_in[2];
    const float* b1   = (const float*)d_in[3];
    const float* w2   = (const float*)d_in[4];
    const float* b2   = (const float*)d_in[5];
    const float* lng  = (const float*)d_in[6];
    const float* lnb  = (const float*)d_in[7];
    const float* gnw  = (const float*)d_in[8];
    const float* gnb  = (const float*)d_in[9];
    const float* gnms = (const float*)d_in[10];
    const int*   ei   = (const int*)d_in[11];

    int N = in_sizes[0] / D;
    int E = in_sizes[1] / D;
    int total4 = N * DV;
    int totalChunks = N * 16;

    cudaFuncSetAttribute(k_mlp, cudaFuncAttributeMaxDynamicSharedMemorySize, SMEM_TOTAL);

    k_pre<<<(totalChunks + 1023) / 1024, 256>>>(nh, w1, w2, totalChunks);
    k_scatter<<<(E + 15) / 16, 256>>>(eh, ei, E);
    k_mlp<<<(N + NT - 1) / NT, 256, SMEM_TOTAL>>>(b1, b2, lng, lnb, N);
    k_final<<<(total4 + 511) / 512, 256>>>(nh, gnw, gnb, gnms, 1.f / (float)N,
                                           (float*)d_out, total4);
}

// round 16
// speedup vs baseline: 1.4656x; 1.0401x over previous
#include <cuda_runtime.h>
#include <cuda_fp16.h>
#include <cstdint>

#define D 128
#define DV 32          // D / 4 (float4)
#define EPS 1e-5f
#define NT 64          // nodes per MLP block
#define PA 136         // fp16 tile pitch (272B rows -> conflict-free LDSM)
#define PS 132         // f32 h2 tile pitch
#define MAXN 50000

// Device scratch (allocation-free rule: __device__ globals)
__device__ uint4  g_agg16[(size_t)MAXN * 16];  // fp16 agg [N][128h], 256B/node
__device__ __half g_hln16[(size_t)MAXN * D];   // fp16 post-LayerNorm h [N][D]
__device__ float  g_colsum[D];
__device__ float  g_colsumsq[D];
// Pre-packed fp16 weights in B-fragment register order:
// [kt(8)][nsub(16)][lane(32)] -> uint2{b0,b1}
__device__ uint2  g_w1p[4096];
__device__ uint2  g_w2p[4096];

// SMEM for k_mlp: fp16 tile 64 x PA (17408 B); sS (64 x PS f32 = 33792 B)
// overlays it post-GEMM, so total is sized for sS.
#define SMEM_TOTAL 34816

// ---------------------------------------------------------------------------
// helpers
// ---------------------------------------------------------------------------
__device__ __forceinline__ uint32_t smem_u32(const void* p) {
    return (uint32_t)__cvta_generic_to_shared(p);
}

__device__ __forceinline__ void ldsm_x4(uint32_t* r, uint32_t addr) {
    asm volatile("ldmatrix.sync.aligned.m8n8.x4.shared.b16 {%0,%1,%2,%3}, [%4];"
                 : "=r"(r[0]), "=r"(r[1]), "=r"(r[2]), "=r"(r[3]) : "r"(addr));
}

__device__ __forceinline__ void mma_h(float* d, const uint32_t* a,
                                      const uint32_t* b) {
    asm volatile(
        "mma.sync.aligned.m16n8k16.row.col.f32.f16.f16.f32 "
        "{%0,%1,%2,%3}, {%4,%5,%6,%7}, {%8,%9}, {%0,%1,%2,%3};"
        : "+f"(d[0]), "+f"(d[1]), "+f"(d[2]), "+f"(d[3])
        : "r"(a[0]), "r"(a[1]), "r"(a[2]), "r"(a[3]), "r"(b[0]), "r"(b[1]));
}

__device__ __forceinline__ uint32_t h2(float a, float b) {
    __half2 h; h.x = __float2half_rn(a); h.y = __float2half_rn(b);
    return *(uint32_t*)&h;
}

// ---------------------------------------------------------------------------
// K0: zero fp16 agg (L2-warm for scatter atomics) + stats, pack weights.
// 4 uint4-chunks per thread; first 16 blocks pack W1/W2.
// ---------------------------------------------------------------------------
__global__ void k_pre(const float* __restrict__ w1, const float* __restrict__ w2,
                      int totalChunks) {
    int idx = blockIdx.x * blockDim.x + threadIdx.x;
    int base = blockIdx.x * 1024 + threadIdx.x;
    #pragma unroll
    for (int u = 0; u < 4; ++u) {
        int i = base + u * 256;
        if (i < totalChunks) g_agg16[i] = make_uint4(0u, 0u, 0u, 0u);
    }
    if (idx < D) { g_colsum[idx] = 0.f; g_colsumsq[idx] = 0.f; }
    if (idx >= 4096) return;

    int lane = idx & 31;
    int nsub = (idx >> 5) & 15;
    int kt   = idx >> 9;
    int k0 = kt * 16 + (lane & 3) * 2;
    int n  = nsub * 8 + (lane >> 2);

    {
        uint2 q;
        q.x = h2(w1[(k0    ) * D + n], w1[(k0 + 1) * D + n]);
        q.y = h2(w1[(k0 + 8) * D + n], w1[(k0 + 9) * D + n]);
        g_w1p[idx] = q;
    }
    {
        uint2 q;
        q.x = h2(w2[(k0    ) * D + n], w2[(k0 + 1) * D + n]);
        q.y = h2(w2[(k0 + 8) * D + n], w2[(k0 + 9) * D + n]);
        g_w2p[idx] = q;
    }
}

// ---------------------------------------------------------------------------
// K1: scatter-add messages, fp16 accumulation. 2 edges per warp (16 lanes
// each, 8 channels/lane). nh gathered fp32 (L2-resident; gather bytes proved
// non-binding in R13), eh fp32 streamed; sums rounded to fp16 for the atomic.
// red.global.add.noftz.v4.f16x2 = 16B/lane -> 16 REDG lanes per edge.
// ---------------------------------------------------------------------------
__global__ void k_scatter(const float* __restrict__ nh,
                          const float* __restrict__ eh,
                          const int* __restrict__ ei,
                          int E) {
    int gw   = (blockIdx.x * blockDim.x + threadIdx.x) >> 5;
    int lane = threadIdx.x & 31;
    int e    = gw * 2 + (lane >> 4);
    int lh   = lane & 15;
    if (e >= E) return;
    int src = ei[e];
    int dst = ei[E + e];
    const float4* nh4 = (const float4*)(nh + (size_t)src * D) + lh * 2;
    const float4* eh4 = (const float4*)(eh + (size_t)e * D) + lh * 2;
    float4 a0 = nh4[0];
    float4 a1 = nh4[1];
    float4 b0 = __ldcs(eh4);
    float4 b1 = __ldcs(eh4 + 1);
    uint32_t r0 = h2(a0.x + b0.x, a0.y + b0.y);
    uint32_t r1 = h2(a0.z + b0.z, a0.w + b0.w);
    uint32_t r2 = h2(a1.x + b1.x, a1.y + b1.y);
    uint32_t r3 = h2(a1.z + b1.z, a1.w + b1.w);
    uint4* p = &g_agg16[(size_t)dst * 16 + lh];
    asm volatile("red.global.add.noftz.v4.f16x2 [%0], {%1, %2, %3, %4};"
                 :: "l"(p), "r"(r0), "r"(r1), "r"(r2), "r"(r3)
                 : "memory");
}

// ---------------------------------------------------------------------------
// K2: tensor-core MLP, NT=64 nodes/block, 8 warps. Pure fp16 operands
// (f32 accumulate). agg tile read directly as fp16; hln written as fp16.
// Warp w: mh = w & 1 (32-row half), nq = w >> 1 (32-col quarter).
// ---------------------------------------------------------------------------
__global__ void k_mlp(const float* __restrict__ b1, const float* __restrict__ b2,
                      const float* __restrict__ lng, const float* __restrict__ lnb,
                      int N) {
    extern __shared__ char sb[];
    __half* sHi = (__half*)(sb);
    float*  sS  = (float*)(sb);
    float*  sPartS = (float*)(sb);
    float*  sPartQ = (float*)(sb + 4096);

    const int t    = threadIdx.x;
    const int lane = t & 31;
    const int w    = t >> 5;
    const int nodeBase = blockIdx.x * NT;

    // ---- load agg tile (64 nodes), fp16 passthrough ----
    {
        int n  = t >> 2;             // 0..63
        int k0 = (t & 3) * 32;       // 0,32,64,96
        int gn = nodeBase + n;
        __half* rowHi = sHi + n * PA;
        #pragma unroll
        for (int i = 0; i < 4; ++i) {
            uint4 v = make_uint4(0u, 0u, 0u, 0u);
            if (gn < N) v = g_agg16[(size_t)gn * 16 + (k0 >> 3) + i];
            *(uint4*)((char*)(rowHi + k0 + i * 8)) = v;
        }
    }
    __syncthreads();

    const int mh = w & 1;            // 32-row half
    const int nq = w >> 1;           // 32-col quarter
    const uint32_t aB0 = smem_u32(sHi + (mh * 32 + (lane & 15)) * PA) + (lane >> 4) * 16;
    const uint32_t aB1 = aB0 + 16 * PA * 2;   // +16 rows

    float acc[32];
    #pragma unroll
    for (int i = 0; i < 32; ++i) acc[i] = 0.f;

    // ---- layer 1: h1 = relu(agg @ W1 + b1) ----
    #pragma unroll
    for (int kt = 0; kt < 8; ++kt) {
        uint32_t a0h[4], a1h[4];
        ldsm_x4(a0h, aB0 + kt * 32);
        ldsm_x4(a1h, aB1 + kt * 32);
        #pragma unroll
        for (int s = 0; s < 4; ++s) {
            uint2 q = g_w1p[(kt * 16 + nq * 4 + s) * 32 + lane];
            mma_h(acc + 4 * s,      a0h, &q.x);
            mma_h(acc + 16 + 4 * s, a1h, &q.x);
        }
    }
    __syncthreads();                 // everyone done reading A -> overwrite with H
    #pragma unroll
    for (int m = 0; m < 2; ++m) {
        #pragma unroll
        for (int s = 0; s < 4; ++s) {
            int cb = nq * 32 + s * 8 + (lane & 3) * 2;
            int r0 = mh * 32 + m * 16 + (lane >> 2);
            float2 bb = *(const float2*)(b1 + cb);
            float v00 = fmaxf(acc[16*m + 4*s + 0] + bb.x, 0.f);
            float v01 = fmaxf(acc[16*m + 4*s + 1] + bb.y, 0.f);
            float v10 = fmaxf(acc[16*m + 4*s + 2] + bb.x, 0.f);
            float v11 = fmaxf(acc[16*m + 4*s + 3] + bb.y, 0.f);
            *(uint32_t*)((char*)(sHi + r0 * PA + cb))       = h2(v00, v01);
            *(uint32_t*)((char*)(sHi + (r0 + 8) * PA + cb)) = h2(v10, v11);
        }
    }
    __syncthreads();

    #pragma unroll
    for (int i = 0; i < 32; ++i) acc[i] = 0.f;

    // ---- layer 2: h2 = h1 @ W2 + b2 (H lives in the A region) ----
    #pragma unroll
    for (int kt = 0; kt < 8; ++kt) {
        uint32_t a0h[4], a1h[4];
        ldsm_x4(a0h, aB0 + kt * 32);
        ldsm_x4(a1h, aB1 + kt * 32);
        #pragma unroll
        for (int s = 0; s < 4; ++s) {
            uint2 q = g_w2p[(kt * 16 + nq * 4 + s) * 32 + lane];
            mma_h(acc + 4 * s,      a0h, &q.x);
            mma_h(acc + 16 + 4 * s, a1h, &q.x);
        }
    }
    __syncthreads();                 // H dead -> overwrite with sS
    #pragma unroll
    for (int m = 0; m < 2; ++m) {
        #pragma unroll
        for (int s = 0; s < 4; ++s) {
            int cb = nq * 32 + s * 8 + (lane & 3) * 2;
            int r0 = mh * 32 + m * 16 + (lane >> 2);
            float2 bb = *(const float2*)(b2 + cb);
            *(float2*)(sS + r0 * PS + cb)       = make_float2(acc[16*m + 4*s + 0] + bb.x,
                                                              acc[16*m + 4*s + 1] + bb.y);
            *(float2*)(sS + (r0 + 8) * PS + cb) = make_float2(acc[16*m + 4*s + 2] + bb.x,
                                                              acc[16*m + 4*s + 3] + bb.y);
        }
    }
    __syncthreads();

    // ---- LayerNorm per node (warp per node, 8 nodes/warp) + column partials ----
    float colS[4] = {0.f, 0.f, 0.f, 0.f};
    float colQ[4] = {0.f, 0.f, 0.f, 0.f};

    #pragma unroll
    for (int r = 0; r < 8; ++r) {
        int n  = w + r * 8;          // 0..63
        int gn = nodeBase + n;
        float v0 = sS[n * PS + lane];
        float v1 = sS[n * PS + lane + 32];
        float v2 = sS[n * PS + lane + 64];
        float v3 = sS[n * PS + lane + 96];
        float s = v0 + v1 + v2 + v3;
        float q = v0*v0 + v1*v1 + v2*v2 + v3*v3;
        #pragma unroll
        for (int o = 16; o; o >>= 1) {
            s += __shfl_xor_sync(0xFFFFFFFFu, s, o);
            q += __shfl_xor_sync(0xFFFFFFFFu, q, o);
        }
        float mu  = s * (1.f / 128.f);
        float var = q * (1.f / 128.f) - mu * mu;
        float inv = rsqrtf(var + EPS);
        if (gn < N) {
            float y0 = (v0 - mu) * inv * lng[lane]      + lnb[lane];
            float y1 = (v1 - mu) * inv * lng[lane + 32] + lnb[lane + 32];
            float y2 = (v2 - mu) * inv * lng[lane + 64] + lnb[lane + 64];
            float y3 = (v3 - mu) * inv * lng[lane + 96] + lnb[lane + 96];
            __half* hp = g_hln16 + (size_t)gn * D;
            hp[lane]      = __float2half_rn(y0);
            hp[lane + 32] = __float2half_rn(y1);
            hp[lane + 64] = __float2half_rn(y2);
            hp[lane + 96] = __float2half_rn(y3);
            colS[0] += y0; colQ[0] += y0 * y0;
            colS[1] += y1; colQ[1] += y1 * y1;
            colS[2] += y2; colQ[2] += y2 * y2;
            colS[3] += y3; colQ[3] += y3 * y3;
        }
    }
    __syncthreads();                 // sS dead -> partials
    #pragma unroll
    for (int qq = 0; qq < 4; ++qq) {
        sPartS[w * D + lane + 32 * qq] = colS[qq];
        sPartQ[w * D + lane + 32 * qq] = colQ[qq];
    }
    __syncthreads();
    if (t < D) {
        float s = 0.f, q = 0.f;
        #pragma unroll
        for (int w8 = 0; w8 < 8; ++w8) {
            s += sPartS[w8 * D + t];
            q += sPartQ[w8 * D + t];
        }
        atomicAdd(&g_colsum[t], s);
        atomicAdd(&g_colsumsq[t], q);
    }
}

// ---------------------------------------------------------------------------
// K4: out = relu((hln - ms*gmu) * mul + gn_b) + node_hidden.
// total4 = 50000*32 = 3125*512 exactly -> no bounds check; loads batch first.
// ---------------------------------------------------------------------------
__global__ void k_final(const float* __restrict__ nh,
                        const float* __restrict__ gnw,
                        const float* __restrict__ gnb,
                        const float* __restrict__ gnms,
                        float invN,
                        float* __restrict__ out,
                        int total4) {
    __shared__ float sMul[D], sSub[D], sB[D];
    int t = threadIdx.x;
    if (t < D) {
        float gmu = g_colsum[t] * invN;
        float e2  = g_colsumsq[t] * invN;
        float ms  = gnms[t];
        float gvar = e2 - 2.f * ms * gmu * gmu + ms * ms * gmu * gmu;
        sMul[t] = rsqrtf(gvar + EPS) * gnw[t];
        sSub[t] = ms * gmu;
        sB[t]   = gnb[t];
    }
    __syncthreads();
    int i0 = blockIdx.x * 512 + t;
    int i1 = i0 + 256;
    uint2  hv0 = ((const uint2*)g_hln16)[i0];
    uint2  hv1 = ((const uint2*)g_hln16)[i1];
    float4 x0  = ((const float4*)nh)[i0];
    float4 x1  = ((const float4*)nh)[i1];
    {
        int c4 = (i0 & (DV - 1)) * 4;
        float2 h0 = __half22float2(*(__half2*)&hv0.x);
        float2 h1 = __half22float2(*(__half2*)&hv0.y);
        float4 o;
        o.x = fmaxf((h0.x - sSub[c4 + 0]) * sMul[c4 + 0] + sB[c4 + 0], 0.f) + x0.x;
        o.y = fmaxf((h0.y - sSub[c4 + 1]) * sMul[c4 + 1] + sB[c4 + 1], 0.f) + x0.y;
        o.z = fmaxf((h1.x - sSub[c4 + 2]) * sMul[c4 + 2] + sB[c4 + 2], 0.f) + x0.z;
        o.w = fmaxf((h1.y - sSub[c4 + 3]) * sMul[c4 + 3] + sB[c4 + 3], 0.f) + x0.w;
        ((float4*)out)[i0] = o;
    }
    {
        int c4 = (i1 & (DV - 1)) * 4;
        float2 h0 = __half22float2(*(__half2*)&hv1.x);
        float2 h1 = __half22float2(*(__half2*)&hv1.y);
        float4 o;
        o.x = fmaxf((h0.x - sSub[c4 + 0]) * sMul[c4 + 0] + sB[c4 + 0], 0.f) + x1.x;
        o.y = fmaxf((h0.y - sSub[c4 + 1]) * sMul[c4 + 1] + sB[c4 + 1], 0.f) + x1.y;
        o.z = fmaxf((h1.x - sSub[c4 + 2]) * sMul[c4 + 2] + sB[c4 + 2], 0.f) + x1.z;
        o.w = fmaxf((h1.y - sSub[c4 + 3]) * sMul[c4 + 3] + sB[c4 + 3], 0.f) + x1.w;
        ((float4*)out)[i1] = o;
    }
}

// ---------------------------------------------------------------------------
extern "C" void kernel_launch(void* const* d_in, const int* in_sizes, int n_in,
                              void* d_out, int out_size) {
    const float* nh   = (const float*)d_in[0];
    const float* eh   = (const float*)d_in[1];
    const float* w1   = (const float*)d_in[2];
    const float* b1   = (const float*)d_in[3];
    const float* w2   = (const float*)d_in[4];
    const float* b2   = (const float*)d_in[5];
    const float* lng  = (const float*)d_in[6];
    const float* lnb  = (const float*)d_in[7];
    const float* gnw  = (const float*)d_in[8];
    const float* gnb  = (const float*)d_in[9];
    const float* gnms = (const float*)d_in[10];
    const int*   ei   = (const int*)d_in[11];

    int N = in_sizes[0] / D;
    int E = in_sizes[1] / D;
    int total4 = N * DV;
    int totalChunks = N * 16;

    cudaFuncSetAttribute(k_mlp, cudaFuncAttributeMaxDynamicSharedMemorySize, SMEM_TOTAL);

    k_pre<<<(totalChunks + 1023) / 1024, 256>>>(w1, w2, totalChunks);
    k_scatter<<<(E + 15) / 16, 256>>>(nh, eh, ei, E);
    k_mlp<<<(N + NT - 1) / NT, 256, SMEM_TOTAL>>>(b1, b2, lng, lnb, N);
    k_final<<<(total4 + 511) / 512, 256>>>(nh, gnw, gnb, gnms, 1.f / (float)N,
                                           (float*)d_out, total4);
}

// round 17
// speedup vs baseline: 1.4701x; 1.0030x over previous
#include <cuda_runtime.h>
#include <cuda_fp16.h>
#include <cstdint>

#define D 128
#define DV 32          // D / 4 (float4)
#define EPS 1e-5f
#define NT 64          // nodes per MLP block
#define PA 136         // fp16 tile pitch (272B rows -> conflict-free LDSM)
#define MAXN 50000

// Device scratch (allocation-free rule: __device__ globals)
__device__ uint4  g_agg16[(size_t)MAXN * 16];  // fp16 agg [N][128h], 256B/node
__device__ __half g_hln16[(size_t)MAXN * D];   // fp16 post-LayerNorm h [N][D]
__device__ float  g_colsum[D];
__device__ float  g_colsumsq[D];
// Pre-packed fp16 weights in B-fragment register order:
// [kt(8)][nsub(16)][lane(32)] -> uint2{b0,b1}
__device__ uint2  g_w1p[4096];
__device__ uint2  g_w2p[4096];

// SMEM for k_mlp: fp16 tile 64 x PA = 17408 B. The LN exchange buffers
// (sRow 2048B, sColS/Q 1024B) overlay the tile after the last ldsm.
#define SMEM_TOTAL 17408

// ---------------------------------------------------------------------------
// helpers
// ---------------------------------------------------------------------------
__device__ __forceinline__ uint32_t smem_u32(const void* p) {
    return (uint32_t)__cvta_generic_to_shared(p);
}

__device__ __forceinline__ void ldsm_x4(uint32_t* r, uint32_t addr) {
    asm volatile("ldmatrix.sync.aligned.m8n8.x4.shared.b16 {%0,%1,%2,%3}, [%4];"
                 : "=r"(r[0]), "=r"(r[1]), "=r"(r[2]), "=r"(r[3]) : "r"(addr));
}

__device__ __forceinline__ void mma_h(float* d, const uint32_t* a,
                                      const uint32_t* b) {
    asm volatile(
        "mma.sync.aligned.m16n8k16.row.col.f32.f16.f16.f32 "
        "{%0,%1,%2,%3}, {%4,%5,%6,%7}, {%8,%9}, {%0,%1,%2,%3};"
        : "+f"(d[0]), "+f"(d[1]), "+f"(d[2]), "+f"(d[3])
        : "r"(a[0]), "r"(a[1]), "r"(a[2]), "r"(a[3]), "r"(b[0]), "r"(b[1]));
}

__device__ __forceinline__ uint32_t h2(float a, float b) {
    __half2 h; h.x = __float2half_rn(a); h.y = __float2half_rn(b);
    return *(uint32_t*)&h;
}

// ---------------------------------------------------------------------------
// K0: zero fp16 agg (L2-warm for scatter atomics) + stats, pack weights.
// ---------------------------------------------------------------------------
__global__ void k_pre(const float* __restrict__ w1, const float* __restrict__ w2,
                      int totalChunks) {
    int idx = blockIdx.x * blockDim.x + threadIdx.x;
    int base = blockIdx.x * 1024 + threadIdx.x;
    #pragma unroll
    for (int u = 0; u < 4; ++u) {
        int i = base + u * 256;
        if (i < totalChunks) g_agg16[i] = make_uint4(0u, 0u, 0u, 0u);
    }
    if (idx < D) { g_colsum[idx] = 0.f; g_colsumsq[idx] = 0.f; }
    if (idx >= 4096) return;

    int lane = idx & 31;
    int nsub = (idx >> 5) & 15;
    int kt   = idx >> 9;
    int k0 = kt * 16 + (lane & 3) * 2;
    int n  = nsub * 8 + (lane >> 2);

    {
        uint2 q;
        q.x = h2(w1[(k0    ) * D + n], w1[(k0 + 1) * D + n]);
        q.y = h2(w1[(k0 + 8) * D + n], w1[(k0 + 9) * D + n]);
        g_w1p[idx] = q;
    }
    {
        uint2 q;
        q.x = h2(w2[(k0    ) * D + n], w2[(k0 + 1) * D + n]);
        q.y = h2(w2[(k0 + 8) * D + n], w2[(k0 + 9) * D + n]);
        g_w2p[idx] = q;
    }
}

// ---------------------------------------------------------------------------
// K1: scatter-add messages, fp16 accumulation (proven R16 form).
// ---------------------------------------------------------------------------
__global__ void k_scatter(const float* __restrict__ nh,
                          const float* __restrict__ eh,
                          const int* __restrict__ ei,
                          int E) {
    int gw   = (blockIdx.x * blockDim.x + threadIdx.x) >> 5;
    int lane = threadIdx.x & 31;
    int e    = gw * 2 + (lane >> 4);
    int lh   = lane & 15;
    if (e >= E) return;
    int src = ei[e];
    int dst = ei[E + e];
    const float4* nh4 = (const float4*)(nh + (size_t)src * D) + lh * 2;
    const float4* eh4 = (const float4*)(eh + (size_t)e * D) + lh * 2;
    float4 a0 = nh4[0];
    float4 a1 = nh4[1];
    float4 b0 = __ldcs(eh4);
    float4 b1 = __ldcs(eh4 + 1);
    uint32_t r0 = h2(a0.x + b0.x, a0.y + b0.y);
    uint32_t r1 = h2(a0.z + b0.z, a0.w + b0.w);
    uint32_t r2 = h2(a1.x + b1.x, a1.y + b1.y);
    uint32_t r3 = h2(a1.z + b1.z, a1.w + b1.w);
    uint4* p = &g_agg16[(size_t)dst * 16 + lh];
    asm volatile("red.global.add.noftz.v4.f16x2 [%0], {%1, %2, %3, %4};"
                 :: "l"(p), "r"(r0), "r"(r1), "r"(r2), "r"(r3)
                 : "memory");
}

// ---------------------------------------------------------------------------
// K2: tensor-core MLP, NT=64 nodes/block, 8 warps, pure fp16 operands.
// Register-resident LN epilogue: no sS tile; cross-warp row partials go
// through a 2KB sRow exchange; hln written straight from registers.
// Warp w: mh = w & 1 (32-row half), nq = w >> 1 (32-col quarter).
// Lane layout per warp tile (m32 x n32):
//   rows  = mh*32 + m*16 + (lane>>2) + rr*8   (m,rr in {0,1})
//   cols  = nq*32 + s*8 + (lane&3)*2 + j      (s in 0..3, j in {0,1})
//   acc[16*m + 4*s + rr*2 + j]
// ---------------------------------------------------------------------------
__global__ void k_mlp(const float* __restrict__ b1, const float* __restrict__ b2,
                      const float* __restrict__ lng, const float* __restrict__ lnb,
                      int N) {
    extern __shared__ char sb[];
    __half* sHi = (__half*)(sb);
    float2* sRow  = (float2*)(sb);           // [64][4] (row partials: s,q)
    float*  sColS = (float*)(sb + 2048);     // [128]
    float*  sColQ = (float*)(sb + 2560);     // [128]

    const int t    = threadIdx.x;
    const int lane = t & 31;
    const int w    = t >> 5;
    const int nodeBase = blockIdx.x * NT;

    // ---- load agg tile (64 nodes), fp16 passthrough ----
    {
        int n  = t >> 2;             // 0..63
        int k0 = (t & 3) * 32;       // 0,32,64,96
        int gn = nodeBase + n;
        __half* rowHi = sHi + n * PA;
        #pragma unroll
        for (int i = 0; i < 4; ++i) {
            uint4 v = make_uint4(0u, 0u, 0u, 0u);
            if (gn < N) v = g_agg16[(size_t)gn * 16 + (k0 >> 3) + i];
            *(uint4*)((char*)(rowHi + k0 + i * 8)) = v;
        }
    }
    __syncthreads();

    const int mh = w & 1;            // 32-row half
    const int nq = w >> 1;           // 32-col quarter
    const uint32_t aB0 = smem_u32(sHi + (mh * 32 + (lane & 15)) * PA) + (lane >> 4) * 16;
    const uint32_t aB1 = aB0 + 16 * PA * 2;   // +16 rows

    float acc[32];
    #pragma unroll
    for (int i = 0; i < 32; ++i) acc[i] = 0.f;

    // ---- layer 1: h1 = relu(agg @ W1 + b1) ----
    #pragma unroll
    for (int kt = 0; kt < 8; ++kt) {
        uint32_t a0h[4], a1h[4];
        ldsm_x4(a0h, aB0 + kt * 32);
        ldsm_x4(a1h, aB1 + kt * 32);
        #pragma unroll
        for (int s = 0; s < 4; ++s) {
            uint2 q = g_w1p[(kt * 16 + nq * 4 + s) * 32 + lane];
            mma_h(acc + 4 * s,      a0h, &q.x);
            mma_h(acc + 16 + 4 * s, a1h, &q.x);
        }
    }
    __syncthreads();                 // everyone done reading A -> overwrite with H
    #pragma unroll
    for (int m = 0; m < 2; ++m) {
        #pragma unroll
        for (int s = 0; s < 4; ++s) {
            int cb = nq * 32 + s * 8 + (lane & 3) * 2;
            int r0 = mh * 32 + m * 16 + (lane >> 2);
            float2 bb = *(const float2*)(b1 + cb);
            float v00 = fmaxf(acc[16*m + 4*s + 0] + bb.x, 0.f);
            float v01 = fmaxf(acc[16*m + 4*s + 1] + bb.y, 0.f);
            float v10 = fmaxf(acc[16*m + 4*s + 2] + bb.x, 0.f);
            float v11 = fmaxf(acc[16*m + 4*s + 3] + bb.y, 0.f);
            *(uint32_t*)((char*)(sHi + r0 * PA + cb))       = h2(v00, v01);
            *(uint32_t*)((char*)(sHi + (r0 + 8) * PA + cb)) = h2(v10, v11);
        }
    }
    __syncthreads();

    #pragma unroll
    for (int i = 0; i < 32; ++i) acc[i] = 0.f;

    // ---- layer 2: h2 = h1 @ W2 + b2 (H lives in the A region) ----
    #pragma unroll
    for (int kt = 0; kt < 8; ++kt) {
        uint32_t a0h[4], a1h[4];
        ldsm_x4(a0h, aB0 + kt * 32);
        ldsm_x4(a1h, aB1 + kt * 32);
        #pragma unroll
        for (int s = 0; s < 4; ++s) {
            uint2 q = g_w2p[(kt * 16 + nq * 4 + s) * 32 + lane];
            mma_h(acc + 4 * s,      a0h, &q.x);
            mma_h(acc + 16 + 4 * s, a1h, &q.x);
        }
    }

    // ---- add bias in registers ----
    #pragma unroll
    for (int m = 0; m < 2; ++m) {
        #pragma unroll
        for (int s = 0; s < 4; ++s) {
            int cb = nq * 32 + s * 8 + (lane & 3) * 2;
            float2 bb = *(const float2*)(b2 + cb);
            acc[16*m + 4*s + 0] += bb.x;
            acc[16*m + 4*s + 1] += bb.y;
            acc[16*m + 4*s + 2] += bb.x;
            acc[16*m + 4*s + 3] += bb.y;
        }
    }

    // ---- per-row partial sums (this warp's 32-channel quarter) ----
    float rs[4], rq[4];              // [m*2+rr]
    #pragma unroll
    for (int m = 0; m < 2; ++m) {
        #pragma unroll
        for (int rr = 0; rr < 2; ++rr) {
            float s = 0.f, q = 0.f;
            #pragma unroll
            for (int si = 0; si < 4; ++si) {
                float a = acc[16*m + 4*si + rr*2 + 0];
                float b = acc[16*m + 4*si + rr*2 + 1];
                s += a + b;
                q += a*a + b*b;
            }
            s += __shfl_xor_sync(0xFFFFFFFFu, s, 1);
            s += __shfl_xor_sync(0xFFFFFFFFu, s, 2);
            q += __shfl_xor_sync(0xFFFFFFFFu, q, 1);
            q += __shfl_xor_sync(0xFFFFFFFFu, q, 2);
            rs[m*2 + rr] = s;
            rq[m*2 + rr] = q;
        }
    }
    __syncthreads();                 // tile fully consumed -> overlay exchange bufs

    if ((lane & 3) == 0) {
        #pragma unroll
        for (int m = 0; m < 2; ++m)
            #pragma unroll
            for (int rr = 0; rr < 2; ++rr) {
                int row = mh * 32 + m * 16 + (lane >> 2) + rr * 8;
                sRow[row * 4 + nq] = make_float2(rs[m*2 + rr], rq[m*2 + rr]);
            }
    }
    if (t < D) { sColS[t] = 0.f; sColQ[t] = 0.f; }
    __syncthreads();

    // ---- finalize LN per row, write hln16, accumulate channel partials ----
    float lg0[4], lg1[4], lb0[4], lb1[4];
    #pragma unroll
    for (int s = 0; s < 4; ++s) {
        int cb = nq * 32 + s * 8 + (lane & 3) * 2;
        float2 g = *(const float2*)(lng + cb);
        float2 b = *(const float2*)(lnb + cb);
        lg0[s] = g.x; lg1[s] = g.y; lb0[s] = b.x; lb1[s] = b.y;
    }
    float cS[8], cQ[8];
    #pragma unroll
    for (int i = 0; i < 8; ++i) { cS[i] = 0.f; cQ[i] = 0.f; }

    #pragma unroll
    for (int m = 0; m < 2; ++m) {
        #pragma unroll
        for (int rr = 0; rr < 2; ++rr) {
            int row = mh * 32 + m * 16 + (lane >> 2) + rr * 8;
            float2 p0 = sRow[row * 4 + 0];
            float2 p1 = sRow[row * 4 + 1];
            float2 p2 = sRow[row * 4 + 2];
            float2 p3 = sRow[row * 4 + 3];
            float S = p0.x + p1.x + p2.x + p3.x;
            float Q = p0.y + p1.y + p2.y + p3.y;
            float mu  = S * (1.f / 128.f);
            float var = Q * (1.f / 128.f) - mu * mu;
            float inv = rsqrtf(var + EPS);
            int gn = nodeBase + row;
            if (gn < N) {
                __half* hp = g_hln16 + (size_t)gn * D;
                #pragma unroll
                for (int s = 0; s < 4; ++s) {
                    int cb = nq * 32 + s * 8 + (lane & 3) * 2;
                    float y0 = (acc[16*m + 4*s + rr*2 + 0] - mu) * inv * lg0[s] + lb0[s];
                    float y1 = (acc[16*m + 4*s + rr*2 + 1] - mu) * inv * lg1[s] + lb1[s];
                    *(uint32_t*)((char*)hp + cb * 2) = h2(y0, y1);
                    cS[s*2 + 0] += y0; cQ[s*2 + 0] += y0 * y0;
                    cS[s*2 + 1] += y1; cQ[s*2 + 1] += y1 * y1;
                }
            }
        }
    }
    // reduce channel partials across lane>>2 groups (same channels, diff rows)
    #pragma unroll
    for (int i = 0; i < 8; ++i) {
        #pragma unroll
        for (int o = 4; o < 32; o <<= 1) {
            cS[i] += __shfl_xor_sync(0xFFFFFFFFu, cS[i], o);
            cQ[i] += __shfl_xor_sync(0xFFFFFFFFu, cQ[i], o);
        }
    }
    if (lane < 4) {
        #pragma unroll
        for (int s = 0; s < 4; ++s) {
            int cb = nq * 32 + s * 8 + lane * 2;
            atomicAdd(&sColS[cb],     cS[s*2 + 0]);
            atomicAdd(&sColS[cb + 1], cS[s*2 + 1]);
            atomicAdd(&sColQ[cb],     cQ[s*2 + 0]);
            atomicAdd(&sColQ[cb + 1], cQ[s*2 + 1]);
        }
    }
    __syncthreads();
    if (t < D) {
        atomicAdd(&g_colsum[t], sColS[t]);
        atomicAdd(&g_colsumsq[t], sColQ[t]);
    }
}

// ---------------------------------------------------------------------------
// K4: out = relu((hln - ms*gmu) * mul + gn_b) + node_hidden.
// total4 = 3125*512 exactly -> no bounds check; loads batch first.
// ---------------------------------------------------------------------------
__global__ void k_final(const float* __restrict__ nh,
                        const float* __restrict__ gnw,
                        const float* __restrict__ gnb,
                        const float* __restrict__ gnms,
                        float invN,
                        float* __restrict__ out,
                        int total4) {
    __shared__ float sMul[D], sSub[D], sB[D];
    int t = threadIdx.x;
    if (t < D) {
        float gmu = g_colsum[t] * invN;
        float e2  = g_colsumsq[t] * invN;
        float ms  = gnms[t];
        float gvar = e2 - 2.f * ms * gmu * gmu + ms * ms * gmu * gmu;
        sMul[t] = rsqrtf(gvar + EPS) * gnw[t];
        sSub[t] = ms * gmu;
        sB[t]   = gnb[t];
    }
    __syncthreads();
    int i0 = blockIdx.x * 512 + t;
    int i1 = i0 + 256;
    uint2  hv0 = ((const uint2*)g_hln16)[i0];
    uint2  hv1 = ((const uint2*)g_hln16)[i1];
    float4 x0  = ((const float4*)nh)[i0];
    float4 x1  = ((const float4*)nh)[i1];
    {
        int c4 = (i0 & (DV - 1)) * 4;
        float2 h0 = __half22float2(*(__half2*)&hv0.x);
        float2 h1 = __half22float2(*(__half2*)&hv0.y);
        float4 o;
        o.x = fmaxf((h0.x - sSub[c4 + 0]) * sMul[c4 + 0] + sB[c4 + 0], 0.f) + x0.x;
        o.y = fmaxf((h0.y - sSub[c4 + 1]) * sMul[c4 + 1] + sB[c4 + 1], 0.f) + x0.y;
        o.z = fmaxf((h1.x - sSub[c4 + 2]) * sMul[c4 + 2] + sB[c4 + 2], 0.f) + x0.z;
        o.w = fmaxf((h1.y - sSub[c4 + 3]) * sMul[c4 + 3] + sB[c4 + 3], 0.f) + x0.w;
        ((float4*)out)[i0] = o;
    }
    {
        int c4 = (i1 & (DV - 1)) * 4;
        float2 h0 = __half22float2(*(__half2*)&hv1.x);
        float2 h1 = __half22float2(*(__half2*)&hv1.y);
        float4 o;
        o.x = fmaxf((h0.x - sSub[c4 + 0]) * sMul[c4 + 0] + sB[c4 + 0], 0.f) + x1.x;
        o.y = fmaxf((h0.y - sSub[c4 + 1]) * sMul[c4 + 1] + sB[c4 + 1], 0.f) + x1.y;
        o.z = fmaxf((h1.x - sSub[c4 + 2]) * sMul[c4 + 2] + sB[c4 + 2], 0.f) + x1.z;
        o.w = fmaxf((h1.y - sSub[c4 + 3]) * sMul[c4 + 3] + sB[c4 + 3], 0.f) + x1.w;
        ((float4*)out)[i1] = o;
    }
}

// ---------------------------------------------------------------------------
extern "C" void kernel_launch(void* const* d_in, const int* in_sizes, int n_in,
                              void* d_out, int out_size) {
    const float* nh   = (const float*)d_in[0];
    const float* eh   = (const float*)d_in[1];
    const float* w1   = (const float*)d_in[2];
    const float* b1   = (const float*)d_in[3];
    const float* w2   = (const float*)d_in[4];
    const float* b2   = (const float*)d_in[5];
    const float* lng  = (const float*)d_in[6];
    const float* lnb  = (const float*)d_in[7];
    const float* gnw  = (const float*)d_in[8];
    const float* gnb  = (const float*)d_in[9];
    const float* gnms = (const float*)d_in[10];
    const int*   ei   = (const int*)d_in[11];

    int N = in_sizes[0] / D;
    int E = in_sizes[1] / D;
    int total4 = N * DV;
    int totalChunks = N * 16;

    cudaFuncSetAttribute(k_mlp, cudaFuncAttributeMaxDynamicSharedMemorySize, SMEM_TOTAL);

    k_pre<<<(totalChunks + 1023) / 1024, 256>>>(w1, w2, totalChunks);
    k_scatter<<<(E + 15) / 16, 256>>>(nh, eh, ei, E);
    k_mlp<<<(N + NT - 1) / NT, 256, SMEM_TOTAL>>>(b1, b2, lng, lnb, N);
    k_final<<<(total4 + 511) / 512, 256>>>(nh, gnw, gnb, gnms, 1.f / (float)N,
                                           (float*)d_out, total4);
}